// round 3
// baseline (speedup 1.0000x reference)
#include <cuda_runtime.h>
#include <cuda_bf16.h>

#define B_TOT 32768
#define EMB   256
#define ADIM  64
#define NH    2
#define KN    16

// Scratch (device globals; no allocation allowed)
__device__ float g_QK [B_TOT * NH * EMB];  // [b][h][d]  -> 64 MB
__device__ float g_CTX[B_TOT * NH * EMB];  // [b][h*256+d] -> 64 MB

// ---------------------------------------------------------------------------
// K1: QK[b,h,:] = (center[b] @ W_q[h]^T) @ W_k[h]
// One block handles 16 b-rows. 256 threads.
// ---------------------------------------------------------------------------
__global__ __launch_bounds__(256) void k1_qk(
    const float* __restrict__ center,
    const float* __restrict__ Wq,   // [128][256]  (h*64+a, d)
    const float* __restrict__ Wk)   // [128][256]
{
    __shared__ float c_sm[16][256];   // 16 KB
    __shared__ float q_sm[16][128];   // 8 KB
    const int b0 = blockIdx.x * 16;
    const int t  = threadIdx.x;

    // load 16 center rows (1024 float4)
    {
        const float4* src = (const float4*)(center + (size_t)b0 * EMB);
        float4* dst = (float4*)&c_sm[0][0];
        #pragma unroll
        for (int i = 0; i < 4; i++) dst[t + i * 256] = src[t + i * 256];
    }
    __syncthreads();

    // Phase 1: q[row][col], col = h*64+a.  thread: col = t&127, rows half t>>7
    {
        const int col = t & 127;
        const int rh  = t >> 7;                 // 0/1 -> rows rh*8 .. rh*8+7
        float acc[8];
        #pragma unroll
        for (int r = 0; r < 8; r++) acc[r] = 0.f;
        const float4* w4 = (const float4*)(Wq + col * EMB);
        #pragma unroll 4
        for (int i = 0; i < 64; i++) {
            const float4 w = __ldg(&w4[i]);
            #pragma unroll
            for (int r = 0; r < 8; r++) {
                const float4 c = *(const float4*)&c_sm[rh * 8 + r][i * 4];
                acc[r] += w.x * c.x + w.y * c.y + w.z * c.z + w.w * c.w;
            }
        }
        #pragma unroll
        for (int r = 0; r < 8; r++) q_sm[rh * 8 + r][col] = acc[r];
    }
    __syncthreads();

    // Phase 2: qk[row][h][d], d = t (0..255)
    {
        const int d = t;
        #pragma unroll
        for (int h = 0; h < NH; h++) {
            float acc[16];
            #pragma unroll
            for (int r = 0; r < 16; r++) acc[r] = 0.f;
            #pragma unroll 4
            for (int a4 = 0; a4 < 16; a4++) {
                const int abase = h * 64 + a4 * 4;
                const float w0 = __ldg(&Wk[(abase + 0) * EMB + d]);
                const float w1 = __ldg(&Wk[(abase + 1) * EMB + d]);
                const float w2 = __ldg(&Wk[(abase + 2) * EMB + d]);
                const float w3 = __ldg(&Wk[(abase + 3) * EMB + d]);
                #pragma unroll
                for (int r = 0; r < 16; r++) {
                    const float4 q = *(const float4*)&q_sm[r][abase];
                    acc[r] += q.x * w0 + q.y * w1 + q.z * w2 + q.w * w3;
                }
            }
            #pragma unroll
            for (int r = 0; r < 16; r++)
                g_QK[((size_t)(b0 + r) * NH + h) * EMB + d] = acc[r];
        }
    }
}

// ---------------------------------------------------------------------------
// K2: scores -> softmax*weights -> renorm -> ctx.  One block (128 thr) per b.
// ---------------------------------------------------------------------------
__global__ __launch_bounds__(128) void k2_attn(
    const float* __restrict__ neigh,   // [B][16][256]
    const float* __restrict__ nw)      // [B][16]
{
    const int b = blockIdx.x;
    const int t = threadIdx.x;
    __shared__ float qk_sm[NH][EMB];
    __shared__ float sc_part[32][4];
    __shared__ float attn_sm[NH][KN];

    // load QK[b] (512 floats = 128 float4)
    ((float4*)&qk_sm[0][0])[t] = __ldg((const float4*)(g_QK + (size_t)b * 512) + t);
    __syncthreads();

    // partial dot products: hj = t>>2 (h = hj>>4, j = hj&15), quarter = t&3
    {
        const int hj = t >> 2, q4 = t & 3;
        const int h = hj >> 4, j = hj & 15;
        const float4* n4 = (const float4*)(neigh + ((size_t)b * KN + j) * EMB + q4 * 64);
        const float4* k4 = (const float4*)&qk_sm[h][q4 * 64];
        float p = 0.f;
        #pragma unroll
        for (int i = 0; i < 16; i++) {
            const float4 n = __ldg(&n4[i]);
            const float4 q = k4[i];
            p += n.x * q.x + n.y * q.y + n.z * q.z + n.w * q.w;
        }
        sc_part[hj][q4] = p;
    }
    __syncthreads();
    if (t < 32) {
        const float s = (sc_part[t][0] + sc_part[t][1] + sc_part[t][2] + sc_part[t][3]) * 0.125f;
        sc_part[t][0] = s;   // scores[hj]
    }
    __syncthreads();
    if (t < 2) {
        const int h = t;
        float s[KN];
        float m = -1e30f;
        #pragma unroll
        for (int j = 0; j < KN; j++) { s[j] = sc_part[h * 16 + j][0]; m = fmaxf(m, s[j]); }
        float Se = 0.f;
        #pragma unroll
        for (int j = 0; j < KN; j++) { s[j] = expf(s[j] - m); Se += s[j]; }
        const float inv = 1.0f / Se;
        float den = 0.f;
        #pragma unroll
        for (int j = 0; j < KN; j++) {
            s[j] = s[j] * inv * __ldg(&nw[(size_t)b * KN + j]);
            den += s[j];
        }
        const float invd = 1.0f / (den + 1e-8f);
        #pragma unroll
        for (int j = 0; j < KN; j++) attn_sm[h][j] = s[j] * invd;
    }
    __syncthreads();

    // ctx[h][d]: 512 outputs, 4 per thread (o = t + i*128 == h*256+d)
    #pragma unroll
    for (int i = 0; i < 4; i++) {
        const int o = t + i * 128;
        const int h = o >> 8, d = o & 255;
        float acc = 0.f;
        #pragma unroll
        for (int j = 0; j < KN; j++)
            acc += attn_sm[h][j] * __ldg(&neigh[((size_t)b * KN + j) * EMB + d]);
        g_CTX[(size_t)b * 512 + o] = acc;
    }
}

// ---------------------------------------------------------------------------
// K3: OUT = CTX @ W_out^T + b_out, then mask.  Tile 32 rows x 256 cols.
// 256 threads; thread computes 8 rows x 4 cols.
// valid_mask arrives as int32 (harness converts bool -> int32).
// ---------------------------------------------------------------------------
__global__ __launch_bounds__(256) void k3_out(
    const float* __restrict__ Wout,    // [256][512]  (e, k)
    const float* __restrict__ bout,    // [256]
    const float* __restrict__ center,  // [B][256]
    const int* __restrict__ mask,      // [B] int32 (0/1)
    float* __restrict__ out)           // [B][256]
{
    __shared__ float ctx_sm[32][128];  // 16 KB chunk
    const int b0 = blockIdx.x * 32;
    const int t  = threadIdx.x;
    const int tc = t & 63;   // cols e = tc*4 .. tc*4+3
    const int tr = t >> 6;   // rows tr*8 .. tr*8+7

    float acc[8][4];
    #pragma unroll
    for (int r = 0; r < 8; r++)
        #pragma unroll
        for (int i = 0; i < 4; i++) acc[r][i] = 0.f;

    for (int ch = 0; ch < 4; ch++) {
        __syncthreads();
        // load ctx chunk [32 rows][128 k] : 1024 float4 / 256 thr = 4 each
        #pragma unroll
        for (int i = 0; i < 4; i++) {
            const int idx = t + i * 256;
            const int row = idx >> 5;      // 32 float4 per row
            const int c4i = idx & 31;
            ((float4*)&ctx_sm[row][0])[c4i] =
                __ldg((const float4*)(g_CTX + (size_t)(b0 + row) * 512 + ch * 128) + c4i);
        }
        __syncthreads();

        const int kbase = ch * 128;
        #pragma unroll 4
        for (int kk = 0; kk < 128; kk++) {
            const int k = kbase + kk;
            const float w0 = __ldg(&Wout[(size_t)(tc * 4 + 0) * 512 + k]);
            const float w1 = __ldg(&Wout[(size_t)(tc * 4 + 1) * 512 + k]);
            const float w2 = __ldg(&Wout[(size_t)(tc * 4 + 2) * 512 + k]);
            const float w3 = __ldg(&Wout[(size_t)(tc * 4 + 3) * 512 + k]);
            #pragma unroll
            for (int r = 0; r < 8; r++) {
                const float c = ctx_sm[tr * 8 + r][kk];
                acc[r][0] += c * w0;
                acc[r][1] += c * w1;
                acc[r][2] += c * w2;
                acc[r][3] += c * w3;
            }
        }
    }

    // epilogue: bias + mask, vectorized stores
    const float4 bias = __ldg((const float4*)bout + tc);
    #pragma unroll
    for (int r = 0; r < 8; r++) {
        const int b = b0 + tr * 8 + r;
        const bool valid = (__ldg(&mask[b]) != 0);
        float4 o4;
        o4.x = acc[r][0] + bias.x;
        o4.y = acc[r][1] + bias.y;
        o4.z = acc[r][2] + bias.z;
        o4.w = acc[r][3] + bias.w;
        if (!valid)
            o4 = __ldg((const float4*)(center + (size_t)b * EMB) + tc);
        *(float4*)(out + (size_t)b * EMB + tc * 4) = o4;
    }
}

// ---------------------------------------------------------------------------
extern "C" void kernel_launch(void* const* d_in, const int* in_sizes, int n_in,
                              void* d_out, int out_size)
{
    const float* center = (const float*)d_in[0];
    const float* neigh  = (const float*)d_in[1];
    const float* nw     = (const float*)d_in[2];
    const int*   vmask  = (const int*)d_in[3];
    const float* Wq     = (const float*)d_in[4];
    const float* Wk     = (const float*)d_in[5];
    const float* Wout   = (const float*)d_in[6];
    const float* bout   = (const float*)d_in[7];
    float*       out    = (float*)d_out;

    k1_qk  <<<B_TOT / 16, 256>>>(center, Wq, Wk);
    k2_attn<<<B_TOT,      128>>>(neigh, nw);
    k3_out <<<B_TOT / 32, 256>>>(Wout, bout, center, vmask, out);
}

// round 4
// speedup vs baseline: 4.0534x; 4.0534x over previous
#include <cuda_runtime.h>
#include <cuda_bf16.h>

#define B_TOT 32768
#define EMB   256
#define ADIM  64
#define NH    2
#define KN    16

// Scratch (device globals; no allocation allowed)
__device__ float g_QK [B_TOT * NH * EMB];  // [b][h][d]
__device__ float g_CTX[B_TOT * NH * EMB];  // [b][h*256+d]

// ---------------------------------------------------------------------------
// K1: QK[b,h,:] = (center[b] @ W_q[h]^T) @ W_k[h]
// One block handles 16 b-rows. 256 threads.
// ---------------------------------------------------------------------------
__global__ __launch_bounds__(256) void k1_qk(
    const float* __restrict__ center,
    const float* __restrict__ Wq,   // [128][256]  (h*64+a, d)
    const float* __restrict__ Wk)   // [128][256]
{
    __shared__ float c_sm[16][256];
    __shared__ float q_sm[16][128];
    const int b0 = blockIdx.x * 16;
    const int t  = threadIdx.x;

    {
        const float4* src = (const float4*)(center + (size_t)b0 * EMB);
        float4* dst = (float4*)&c_sm[0][0];
        #pragma unroll
        for (int i = 0; i < 4; i++) dst[t + i * 256] = src[t + i * 256];
    }
    __syncthreads();

    // Phase 1: q[row][col], col = h*64+a
    {
        const int col = t & 127;
        const int rh  = t >> 7;
        float acc[8];
        #pragma unroll
        for (int r = 0; r < 8; r++) acc[r] = 0.f;
        const float4* w4 = (const float4*)(Wq + col * EMB);
        #pragma unroll 4
        for (int i = 0; i < 64; i++) {
            const float4 w = __ldg(&w4[i]);
            #pragma unroll
            for (int r = 0; r < 8; r++) {
                const float4 c = *(const float4*)&c_sm[rh * 8 + r][i * 4];
                acc[r] += w.x * c.x + w.y * c.y + w.z * c.z + w.w * c.w;
            }
        }
        #pragma unroll
        for (int r = 0; r < 8; r++) q_sm[rh * 8 + r][col] = acc[r];
    }
    __syncthreads();

    // Phase 2: qk[row][h][d], d = t
    {
        const int d = t;
        #pragma unroll
        for (int h = 0; h < NH; h++) {
            float acc[16];
            #pragma unroll
            for (int r = 0; r < 16; r++) acc[r] = 0.f;
            #pragma unroll 4
            for (int a4 = 0; a4 < 16; a4++) {
                const int abase = h * 64 + a4 * 4;
                const float w0 = __ldg(&Wk[(abase + 0) * EMB + d]);
                const float w1 = __ldg(&Wk[(abase + 1) * EMB + d]);
                const float w2 = __ldg(&Wk[(abase + 2) * EMB + d]);
                const float w3 = __ldg(&Wk[(abase + 3) * EMB + d]);
                #pragma unroll
                for (int r = 0; r < 16; r++) {
                    const float4 q = *(const float4*)&q_sm[r][abase];
                    acc[r] += q.x * w0 + q.y * w1 + q.z * w2 + q.w * w3;
                }
            }
            #pragma unroll
            for (int r = 0; r < 16; r++)
                g_QK[((size_t)(b0 + r) * NH + h) * EMB + d] = acc[r];
        }
    }
}

// ---------------------------------------------------------------------------
// K2: single pass over neigh. Block (128 thr) per b. neigh tile staged in
// smem with XOR-16B swizzle so both access patterns are conflict-free.
// ---------------------------------------------------------------------------
__global__ __launch_bounds__(128) void k2_attn(
    const float* __restrict__ neigh,   // [B][16][256]
    const float* __restrict__ nw)      // [B][16]
{
    const int b = blockIdx.x;
    const int t = threadIdx.x;
    __shared__ float n_sm[KN][260];        // swizzled, pad 4
    __shared__ float qk_sm[2 * 256];       // swizzled identically
    __shared__ float s_sm[NH][KN];
    __shared__ float attn_sm[NH][KN];

    // load QK[b] swizzled: f4 index t -> (h, c4)
    {
        const float4 v = __ldg((const float4*)(g_QK + (size_t)b * 512) + t);
        const int h = t >> 6, c4 = t & 63;
        const int phys = c4 ^ ((c4 >> 3) & 7);
        *(float4*)&qk_sm[h * 256 + phys * 4] = v;
    }
    // load neigh tile swizzled: 1024 float4
    {
        const float4* nsrc = (const float4*)(neigh + (size_t)b * KN * EMB);
        #pragma unroll
        for (int i = 0; i < 8; i++) {
            const int f4 = t + i * 128;
            const int j = f4 >> 6, c4 = f4 & 63;
            const int phys = c4 ^ ((c4 >> 3) & 7);
            const float4 v = __ldg(nsrc + f4);
            *(float4*)&n_sm[j][phys * 4] = v;
        }
    }
    __syncthreads();

    // dot phase: thread (j = t>>3, o = t&7) computes partial over 32 floats,
    // both heads from one n read.
    {
        const int j = t >> 3, o = t & 7;
        float a0 = 0.f, a1 = 0.f;
        #pragma unroll
        for (int i = 0; i < 8; i++) {
            const int c4 = o * 8 + i;
            const int phys = c4 ^ o;           // (c4>>3)&7 == o
            const float4 n  = *(const float4*)&n_sm[j][phys * 4];
            const float4 q0 = *(const float4*)&qk_sm[phys * 4];
            const float4 q1 = *(const float4*)&qk_sm[256 + phys * 4];
            a0 += n.x * q0.x + n.y * q0.y + n.z * q0.z + n.w * q0.w;
            a1 += n.x * q1.x + n.y * q1.y + n.z * q1.z + n.w * q1.w;
        }
        // reduce over o (low 3 lane bits)
        #pragma unroll
        for (int m = 1; m < 8; m <<= 1) {
            a0 += __shfl_xor_sync(0xffffffff, a0, m);
            a1 += __shfl_xor_sync(0xffffffff, a1, m);
        }
        if (o == 0) {
            s_sm[0][j] = a0 * 0.125f;   // 1/sqrt(64)
            s_sm[1][j] = a1 * 0.125f;
        }
    }
    __syncthreads();

    if (t < 2) {
        const int h = t;
        float s[KN];
        float m = -1e30f;
        #pragma unroll
        for (int j = 0; j < KN; j++) { s[j] = s_sm[h][j]; m = fmaxf(m, s[j]); }
        float Se = 0.f;
        #pragma unroll
        for (int j = 0; j < KN; j++) { s[j] = expf(s[j] - m); Se += s[j]; }
        const float inv = 1.0f / Se;
        float den = 0.f;
        #pragma unroll
        for (int j = 0; j < KN; j++) {
            s[j] = s[j] * inv * __ldg(&nw[(size_t)b * KN + j]);
            den += s[j];
        }
        const float invd = 1.0f / (den + 1e-8f);
        #pragma unroll
        for (int j = 0; j < KN; j++) attn_sm[h][j] = s[j] * invd;
    }
    __syncthreads();

    // ctx: 4 outputs per thread from smem
    #pragma unroll
    for (int i = 0; i < 4; i++) {
        const int o_idx = t + i * 128;
        const int h = o_idx >> 8, d = o_idx & 255;
        const int c4 = d >> 2;
        const int pd = (c4 ^ ((c4 >> 3) & 7)) * 4 + (d & 3);
        float acc = 0.f;
        #pragma unroll
        for (int j = 0; j < KN; j++)
            acc += attn_sm[h][j] * n_sm[j][pd];
        g_CTX[(size_t)b * 512 + o_idx] = acc;
    }
}

// ---------------------------------------------------------------------------
// K3: OUT = CTX @ W_out^T + b_out, mask epilogue.
// Block: 32 rows x 256 cols, 256 threads, thread = 8 rows x 4 strided cols.
// Wout staged per 32-k chunk in smem (coalesced fill, conflict-free reads).
// ---------------------------------------------------------------------------
__global__ __launch_bounds__(256) void k3_out(
    const float* __restrict__ Wout,    // [256][512]
    const float* __restrict__ bout,    // [256]
    const float* __restrict__ center,  // [B][256]
    const int* __restrict__ mask,      // [B] int32
    float* __restrict__ out)           // [B][256]
{
    __shared__ float w_sm[256][33];    // 33.8 KB
    __shared__ float c_sm[32][33];     // 4.2 KB
    const int b0 = blockIdx.x * 32;
    const int t  = threadIdx.x;
    const int tc = t & 63;             // cols e = tc + 64*i
    const int tr = t >> 6;             // rows tr*8 .. tr*8+7

    float acc[8][4];
    #pragma unroll
    for (int r = 0; r < 8; r++)
        #pragma unroll
        for (int i = 0; i < 4; i++) acc[r][i] = 0.f;

    for (int ch = 0; ch < 16; ch++) {
        __syncthreads();
        // ctx chunk [32 rows][32 k] : 256 float4, 1 per thread
        {
            const int row = t >> 3, kq = t & 7;
            const float4 v = __ldg((const float4*)(g_CTX + (size_t)(b0 + row) * 512 + ch * 32) + kq);
            c_sm[row][kq * 4 + 0] = v.x;
            c_sm[row][kq * 4 + 1] = v.y;
            c_sm[row][kq * 4 + 2] = v.z;
            c_sm[row][kq * 4 + 3] = v.w;
        }
        // w chunk [256 e][32 k] : 2048 float4, 8 per thread
        #pragma unroll
        for (int i = 0; i < 8; i++) {
            const int f4 = t + i * 256;
            const int e = f4 >> 3, kq = f4 & 7;
            const float4 v = __ldg((const float4*)(Wout + (size_t)e * 512 + ch * 32) + kq);
            w_sm[e][kq * 4 + 0] = v.x;
            w_sm[e][kq * 4 + 1] = v.y;
            w_sm[e][kq * 4 + 2] = v.z;
            w_sm[e][kq * 4 + 3] = v.w;
        }
        __syncthreads();

        #pragma unroll 8
        for (int kk = 0; kk < 32; kk++) {
            const float w0 = w_sm[tc      ][kk];
            const float w1 = w_sm[tc +  64][kk];
            const float w2 = w_sm[tc + 128][kk];
            const float w3 = w_sm[tc + 192][kk];
            #pragma unroll
            for (int r = 0; r < 8; r++) {
                const float c = c_sm[tr * 8 + r][kk];
                acc[r][0] += c * w0;
                acc[r][1] += c * w1;
                acc[r][2] += c * w2;
                acc[r][3] += c * w3;
            }
        }
    }

    // epilogue
    float bias[4];
    #pragma unroll
    for (int i = 0; i < 4; i++) bias[i] = __ldg(&bout[tc + 64 * i]);
    #pragma unroll
    for (int r = 0; r < 8; r++) {
        const int b = b0 + tr * 8 + r;
        const bool valid = (__ldg(&mask[b]) != 0);
        #pragma unroll
        for (int i = 0; i < 4; i++) {
            const int e = tc + 64 * i;
            float v = acc[r][i] + bias[i];
            if (!valid) v = __ldg(&center[(size_t)b * EMB + e]);
            out[(size_t)b * EMB + e] = v;
        }
    }
}

// ---------------------------------------------------------------------------
extern "C" void kernel_launch(void* const* d_in, const int* in_sizes, int n_in,
                              void* d_out, int out_size)
{
    const float* center = (const float*)d_in[0];
    const float* neigh  = (const float*)d_in[1];
    const float* nw     = (const float*)d_in[2];
    const int*   vmask  = (const int*)d_in[3];
    const float* Wq     = (const float*)d_in[4];
    const float* Wk     = (const float*)d_in[5];
    const float* Wout   = (const float*)d_in[6];
    const float* bout   = (const float*)d_in[7];
    float*       out    = (float*)d_out;

    k1_qk  <<<B_TOT / 16, 256>>>(center, Wq, Wk);
    k2_attn<<<B_TOT,      128>>>(neigh, nw);
    k3_out <<<B_TOT / 32, 256>>>(Wout, bout, center, vmask, out);
}

// round 5
// speedup vs baseline: 5.3491x; 1.3197x over previous
#include <cuda_runtime.h>
#include <cuda_bf16.h>
#include <cstdint>

#define B_TOT 32768
#define EMB   256
#define ADIM  64
#define NH    2
#define KN    16

// Scratch (device globals; no allocation allowed)
__device__ float g_QK [B_TOT * 512];   // [b][h*256+d]
__device__ float g_CTX[B_TOT * 512];   // [b][h*256+d]
__device__ float g_M  [512 * 256];     // [hd][e] : M[hd,e] = sum_a Wq[h,a,e]*Wk[h,a,d]

__device__ __forceinline__ float f2tf32(float x) {
    float y;
    asm("cvt.rna.tf32.f32 %0, %1;" : "=f"(y) : "f"(x));
    return y;
}

__device__ __forceinline__ void mma_tf32(float c[4], const uint32_t a[4], const uint32_t b[2]) {
    asm volatile(
        "mma.sync.aligned.m16n8k8.row.col.f32.tf32.tf32.f32 "
        "{%0,%1,%2,%3}, {%4,%5,%6,%7}, {%8,%9}, {%0,%1,%2,%3};"
        : "+f"(c[0]), "+f"(c[1]), "+f"(c[2]), "+f"(c[3])
        : "r"(a[0]), "r"(a[1]), "r"(a[2]), "r"(a[3]), "r"(b[0]), "r"(b[1]));
}

// ---------------------------------------------------------------------------
// K0: g_M[hd][e] = sum_a Wq[h*64+a][e] * Wk[h*64+a][d].  512 blocks x 256 thr.
// ---------------------------------------------------------------------------
__global__ __launch_bounds__(256) void k0_M(
    const float* __restrict__ Wq, const float* __restrict__ Wk)
{
    __shared__ float wk_sm[64];
    const int hd = blockIdx.x, h = hd >> 8, d = hd & 255;
    const int t = threadIdx.x;
    if (t < 64) wk_sm[t] = __ldg(&Wk[(h * 64 + t) * 256 + d]);
    __syncthreads();
    float acc = 0.f;
    #pragma unroll 8
    for (int a = 0; a < 64; a++)
        acc += wk_sm[a] * __ldg(&Wq[(h * 64 + a) * 256 + t]);
    g_M[hd * 256 + t] = acc;
}

// ---------------------------------------------------------------------------
// tf32 GEMM: D[m][n] = sum_k A[m][k] * B[n][k]
// Block tile 128x128, 256 threads (8 warps), warp tile 32(M) x 64(N).
// IS_K1: A=param(center), B=g_M, D=g_QK, no epilogue.
// else : A=g_CTX, B=param(Wout), D=param(out), bias+mask epilogue.
// ---------------------------------------------------------------------------
template<int KTOT, bool IS_K1>
__global__ __launch_bounds__(256) void gemm_tf32(
    const float* __restrict__ Ap,
    const float* __restrict__ Bp_in,
    float* __restrict__ Dp_in,
    int NTOT,
    const float* __restrict__ bout,
    const float* __restrict__ center,
    const int* __restrict__ mask)
{
    __shared__ float As[128][36];
    __shared__ float Bs[128][36];

    const float* Aptr = IS_K1 ? Ap   : g_CTX;
    const float* Bptr = IS_K1 ? g_M  : Bp_in;
    float*       Dptr = IS_K1 ? g_QK : Dp_in;

    const int t    = threadIdx.x;
    const int w    = t >> 5, lane = t & 31;
    const int g    = lane >> 2, tid4 = lane & 3;
    const int wm   = w & 3;      // 4 warps along M (32 rows each)
    const int wn   = w >> 2;     // 2 warps along N (64 cols each)
    const int m_blk = blockIdx.x * 128;
    const int n_blk = blockIdx.y * 128;

    float acc[2][8][4];
    #pragma unroll
    for (int mi = 0; mi < 2; mi++)
        #pragma unroll
        for (int ni = 0; ni < 8; ni++)
            #pragma unroll
            for (int i = 0; i < 4; i++) acc[mi][ni][i] = 0.f;

    const int row_s = t >> 3, kq = t & 7;   // staging coords

    for (int ch = 0; ch < KTOT / 32; ch++) {
        __syncthreads();
        #pragma unroll
        for (int i = 0; i < 4; i++) {
            const int rr = row_s + i * 32;
            float4 va = __ldg((const float4*)(Aptr + (size_t)(m_blk + rr) * KTOT + ch * 32) + kq);
            va.x = f2tf32(va.x); va.y = f2tf32(va.y);
            va.z = f2tf32(va.z); va.w = f2tf32(va.w);
            *(float4*)&As[rr][kq * 4] = va;
            float4 vb = __ldg((const float4*)(Bptr + (size_t)(n_blk + rr) * KTOT + ch * 32) + kq);
            vb.x = f2tf32(vb.x); vb.y = f2tf32(vb.y);
            vb.z = f2tf32(vb.z); vb.w = f2tf32(vb.w);
            *(float4*)&Bs[rr][kq * 4] = vb;
        }
        __syncthreads();

        #pragma unroll
        for (int ks = 0; ks < 4; ks++) {
            const int k0 = ks * 8;
            uint32_t af[2][4];
            #pragma unroll
            for (int mi = 0; mi < 2; mi++) {
                const float* ap = &As[wm * 32 + mi * 16 + g][k0 + tid4];
                af[mi][0] = __float_as_uint(ap[0]);
                af[mi][1] = __float_as_uint(ap[8 * 36]);
                af[mi][2] = __float_as_uint(ap[4]);
                af[mi][3] = __float_as_uint(ap[8 * 36 + 4]);
            }
            #pragma unroll
            for (int ni = 0; ni < 8; ni++) {
                uint32_t bf[2];
                const float* bp = &Bs[wn * 64 + ni * 8 + g][k0 + tid4];
                bf[0] = __float_as_uint(bp[0]);
                bf[1] = __float_as_uint(bp[4]);
                mma_tf32(acc[0][ni], af[0], bf);
                mma_tf32(acc[1][ni], af[1], bf);
            }
        }
    }

    // Epilogue.  C frag: c0=(g, 2*tid4), c1=(g, 2*tid4+1), c2=(g+8,..), c3.
    #pragma unroll
    for (int mi = 0; mi < 2; mi++) {
        #pragma unroll
        for (int half = 0; half < 2; half++) {
            const int row = m_blk + wm * 32 + mi * 16 + g + half * 8;
            bool valid = true;
            if (!IS_K1) valid = (__ldg(&mask[row]) != 0);
            #pragma unroll
            for (int ni = 0; ni < 8; ni++) {
                const int col = n_blk + wn * 64 + ni * 8 + tid4 * 2;
                float v0 = acc[mi][ni][half * 2 + 0];
                float v1 = acc[mi][ni][half * 2 + 1];
                if (!IS_K1) {
                    v0 += __ldg(&bout[col]);
                    v1 += __ldg(&bout[col + 1]);
                    if (!valid) {
                        v0 = __ldg(&center[(size_t)row * EMB + col]);
                        v1 = __ldg(&center[(size_t)row * EMB + col + 1]);
                    }
                }
                *(float2*)(Dptr + (size_t)row * NTOT + col) = make_float2(v0, v1);
            }
        }
    }
}

// ---------------------------------------------------------------------------
// K2: single pass over neigh. Block (128 thr) per b. neigh tile staged in
// smem with XOR-16B swizzle so both access patterns are conflict-free.
// ---------------------------------------------------------------------------
__global__ __launch_bounds__(128) void k2_attn(
    const float* __restrict__ neigh,   // [B][16][256]
    const float* __restrict__ nw)      // [B][16]
{
    const int b = blockIdx.x;
    const int t = threadIdx.x;
    __shared__ float n_sm[KN][260];
    __shared__ float qk_sm[2 * 256];
    __shared__ float s_sm[NH][KN];
    __shared__ float attn_sm[NH][KN];

    {
        const float4 v = __ldg((const float4*)(g_QK + (size_t)b * 512) + t);
        const int h = t >> 6, c4 = t & 63;
        const int phys = c4 ^ ((c4 >> 3) & 7);
        *(float4*)&qk_sm[h * 256 + phys * 4] = v;
    }
    {
        const float4* nsrc = (const float4*)(neigh + (size_t)b * KN * EMB);
        #pragma unroll
        for (int i = 0; i < 8; i++) {
            const int f4 = t + i * 128;
            const int j = f4 >> 6, c4 = f4 & 63;
            const int phys = c4 ^ ((c4 >> 3) & 7);
            const float4 v = __ldg(nsrc + f4);
            *(float4*)&n_sm[j][phys * 4] = v;
        }
    }
    __syncthreads();

    {
        const int j = t >> 3, o = t & 7;
        float a0 = 0.f, a1 = 0.f;
        #pragma unroll
        for (int i = 0; i < 8; i++) {
            const int c4 = o * 8 + i;
            const int phys = c4 ^ o;
            const float4 n  = *(const float4*)&n_sm[j][phys * 4];
            const float4 q0 = *(const float4*)&qk_sm[phys * 4];
            const float4 q1 = *(const float4*)&qk_sm[256 + phys * 4];
            a0 += n.x * q0.x + n.y * q0.y + n.z * q0.z + n.w * q0.w;
            a1 += n.x * q1.x + n.y * q1.y + n.z * q1.z + n.w * q1.w;
        }
        #pragma unroll
        for (int m = 1; m < 8; m <<= 1) {
            a0 += __shfl_xor_sync(0xffffffff, a0, m);
            a1 += __shfl_xor_sync(0xffffffff, a1, m);
        }
        if (o == 0) {
            s_sm[0][j] = a0 * 0.125f;
            s_sm[1][j] = a1 * 0.125f;
        }
    }
    __syncthreads();

    if (t < 2) {
        const int h = t;
        float s[KN];
        float m = -1e30f;
        #pragma unroll
        for (int j = 0; j < KN; j++) { s[j] = s_sm[h][j]; m = fmaxf(m, s[j]); }
        float Se = 0.f;
        #pragma unroll
        for (int j = 0; j < KN; j++) { s[j] = expf(s[j] - m); Se += s[j]; }
        const float inv = 1.0f / Se;
        float den = 0.f;
        #pragma unroll
        for (int j = 0; j < KN; j++) {
            s[j] = s[j] * inv * __ldg(&nw[(size_t)b * KN + j]);
            den += s[j];
        }
        const float invd = 1.0f / (den + 1e-8f);
        #pragma unroll
        for (int j = 0; j < KN; j++) attn_sm[h][j] = s[j] * invd;
    }
    __syncthreads();

    #pragma unroll
    for (int i = 0; i < 4; i++) {
        const int o_idx = t + i * 128;
        const int h = o_idx >> 8, d = o_idx & 255;
        const int c4 = d >> 2;
        const int pd = (c4 ^ ((c4 >> 3) & 7)) * 4 + (d & 3);
        float acc = 0.f;
        #pragma unroll
        for (int j = 0; j < KN; j++)
            acc += attn_sm[h][j] * n_sm[j][pd];
        g_CTX[(size_t)b * 512 + o_idx] = acc;
    }
}

// ---------------------------------------------------------------------------
extern "C" void kernel_launch(void* const* d_in, const int* in_sizes, int n_in,
                              void* d_out, int out_size)
{
    const float* center = (const float*)d_in[0];
    const float* neigh  = (const float*)d_in[1];
    const float* nw     = (const float*)d_in[2];
    const int*   vmask  = (const int*)d_in[3];
    const float* Wq     = (const float*)d_in[4];
    const float* Wk     = (const float*)d_in[5];
    const float* Wout   = (const float*)d_in[6];
    const float* bout   = (const float*)d_in[7];
    float*       out    = (float*)d_out;

    k0_M<<<512, 256>>>(Wq, Wk);
    // QK[32768,512] = center[32768,256] @ M^T   (B = g_M [512][256])
    gemm_tf32<256, true><<<dim3(256, 4), 256>>>(center, nullptr, nullptr, 512,
                                                nullptr, nullptr, nullptr);
    k2_attn<<<B_TOT, 128>>>(neigh, nw);
    // OUT[32768,256] = CTX[32768,512] @ Wout^T + bias, masked
    gemm_tf32<512, false><<<dim3(256, 2), 256>>>(nullptr, Wout, out, 256,
                                                 bout, center, vmask);
}

// round 7
// speedup vs baseline: 9.2724x; 1.7335x over previous
#include <cuda_runtime.h>
#include <cuda_bf16.h>
#include <cstdint>

#define B_TOT 32768
#define EMB   256
#define ADIM  64
#define NH    2
#define KN    16

// Scratch (device globals; no allocation allowed)
__device__ float g_QK [B_TOT * 512];   // [b][h*256+d]
__device__ float g_CTX[B_TOT * 512];   // [b][h*256+d]
__device__ float g_M  [512 * 256];     // [hd][e]

__device__ __forceinline__ void mma_tf32(float c[4], const uint32_t a[4], const uint32_t b[2]) {
    asm volatile(
        "mma.sync.aligned.m16n8k8.row.col.f32.tf32.tf32.f32 "
        "{%0,%1,%2,%3}, {%4,%5,%6,%7}, {%8,%9}, {%0,%1,%2,%3};"
        : "+f"(c[0]), "+f"(c[1]), "+f"(c[2]), "+f"(c[3])
        : "r"(a[0]), "r"(a[1]), "r"(a[2]), "r"(a[3]), "r"(b[0]), "r"(b[1]));
}

__device__ __forceinline__ void cp16(uint32_t dst, const void* src) {
    asm volatile("cp.async.cg.shared.global [%0], [%1], 16;" :: "r"(dst), "l"(src));
}
__device__ __forceinline__ void cp_commit() {
    asm volatile("cp.async.commit_group;");
}
template<int N>
__device__ __forceinline__ void cp_wait() {
    asm volatile("cp.async.wait_group %0;" :: "n"(N));
}

// ---------------------------------------------------------------------------
// K0: g_M[hd][e] = sum_a Wq[h*64+a][e] * Wk[h*64+a][d].  512 blocks x 256 thr.
// ---------------------------------------------------------------------------
__global__ __launch_bounds__(256) void k0_M(
    const float* __restrict__ Wq, const float* __restrict__ Wk)
{
    __shared__ float wk_sm[64];
    const int hd = blockIdx.x, h = hd >> 8, d = hd & 255;
    const int t = threadIdx.x;
    if (t < 64) wk_sm[t] = __ldg(&Wk[(h * 64 + t) * 256 + d]);
    __syncthreads();
    float acc = 0.f;
    #pragma unroll 8
    for (int a = 0; a < 64; a++)
        acc += wk_sm[a] * __ldg(&Wq[(h * 64 + a) * 256 + t]);
    g_M[hd * 256 + t] = acc;
}

// ---------------------------------------------------------------------------
// tf32 GEMM, cp.async double-buffered (2 stages x 16-k chunks).
// Block tile 128x128, 256 threads (8 warps), warp tile 32(M) x 64(N).
// Smem layout: [buf][row][16] with float4 XOR swizzle c4p = c4 ^ ((row>>1)&3).
// ---------------------------------------------------------------------------
template<int KTOT, bool IS_K1>
__global__ __launch_bounds__(256) void gemm_tf32(
    const float* __restrict__ Ap,
    const float* __restrict__ Bp_in,
    float* __restrict__ Dp_in,
    int NTOT,
    const float* __restrict__ bout,
    const float* __restrict__ center,
    const int* __restrict__ mask)
{
    __shared__ float As[2][128][16];
    __shared__ float Bs[2][128][16];

    const float* Aptr = IS_K1 ? Ap   : g_CTX;
    const float* Bptr = IS_K1 ? g_M  : Bp_in;
    float*       Dptr = IS_K1 ? g_QK : Dp_in;

    const int t    = threadIdx.x;
    const int w    = t >> 5, lane = t & 31;
    const int g    = lane >> 2, tid4 = lane & 3;
    const int wm   = w & 3;      // 4 warps along M (32 rows each)
    const int wn   = w >> 2;     // 2 warps along N (64 cols each)
    const int m_blk = blockIdx.x * 128;
    const int n_blk = blockIdx.y * 128;

    const uint32_t a_base = (uint32_t)__cvta_generic_to_shared(&As[0][0][0]);
    const uint32_t b_base = (uint32_t)__cvta_generic_to_shared(&Bs[0][0][0]);

    constexpr int NCH = KTOT / 16;

    // staging coords: idx = t + i*256 -> row = idx>>2 (0..127), kq = idx&3
    const int row_st = t >> 2;        // + i*64
    const int kq_st  = t & 3;

    auto stage = [&](int ch, int buf) {
        #pragma unroll
        for (int i = 0; i < 2; i++) {
            const int row = row_st + i * 64;
            const int c4p = kq_st ^ ((row >> 1) & 3);
            const uint32_t off = (uint32_t)(((buf * 128 + row) * 16 + c4p * 4) * 4);
            cp16(a_base + off, Aptr + (size_t)(m_blk + row) * KTOT + ch * 16 + kq_st * 4);
            cp16(b_base + off, Bptr + (size_t)(n_blk + row) * KTOT + ch * 16 + kq_st * 4);
        }
    };

    float acc[2][8][4];
    #pragma unroll
    for (int mi = 0; mi < 2; mi++)
        #pragma unroll
        for (int ni = 0; ni < 8; ni++)
            #pragma unroll
            for (int i = 0; i < 4; i++) acc[mi][ni][i] = 0.f;

    stage(0, 0);
    cp_commit();

    for (int ch = 0; ch < NCH; ch++) {
        const int buf = ch & 1;
        if (ch + 1 < NCH) {
            stage(ch + 1, buf ^ 1);
            cp_commit();
            cp_wait<1>();
        } else {
            cp_wait<0>();
        }
        __syncthreads();

        #pragma unroll
        for (int ks = 0; ks < 2; ks++) {
            const int c4a = ks * 2;                  // k0>>2, k0 = ks*8
            uint32_t af[2][4];
            #pragma unroll
            for (int mi = 0; mi < 2; mi++) {
                const int r0 = wm * 32 + mi * 16 + g;
                const int r1 = r0 + 8;
                const int s0 = (r0 >> 1) & 3;
                const int s1 = (r1 >> 1) & 3;
                af[mi][0] = __float_as_uint(As[buf][r0][((c4a    ) ^ s0) * 4 + tid4]);
                af[mi][1] = __float_as_uint(As[buf][r1][((c4a    ) ^ s1) * 4 + tid4]);
                af[mi][2] = __float_as_uint(As[buf][r0][((c4a + 1) ^ s0) * 4 + tid4]);
                af[mi][3] = __float_as_uint(As[buf][r1][((c4a + 1) ^ s1) * 4 + tid4]);
            }
            #pragma unroll
            for (int ni = 0; ni < 8; ni++) {
                const int rb = wn * 64 + ni * 8 + g;
                const int sb = (rb >> 1) & 3;
                uint32_t bf[2];
                bf[0] = __float_as_uint(Bs[buf][rb][((c4a    ) ^ sb) * 4 + tid4]);
                bf[1] = __float_as_uint(Bs[buf][rb][((c4a + 1) ^ sb) * 4 + tid4]);
                mma_tf32(acc[0][ni], af[0], bf);
                mma_tf32(acc[1][ni], af[1], bf);
            }
        }
        __syncthreads();
    }

    // Epilogue.  C frag: c0=(g, 2*tid4), c1=(g, 2*tid4+1), c2=(g+8,..), c3.
    #pragma unroll
    for (int mi = 0; mi < 2; mi++) {
        #pragma unroll
        for (int half = 0; half < 2; half++) {
            const int row = m_blk + wm * 32 + mi * 16 + g + half * 8;
            bool valid = true;
            if (!IS_K1) valid = (__ldg(&mask[row]) != 0);
            #pragma unroll
            for (int ni = 0; ni < 8; ni++) {
                const int col = n_blk + wn * 64 + ni * 8 + tid4 * 2;
                float v0 = acc[mi][ni][half * 2 + 0];
                float v1 = acc[mi][ni][half * 2 + 1];
                if (!IS_K1) {
                    v0 += __ldg(&bout[col]);
                    v1 += __ldg(&bout[col + 1]);
                    if (!valid) {
                        v0 = __ldg(&center[(size_t)row * EMB + col]);
                        v1 = __ldg(&center[(size_t)row * EMB + col + 1]);
                    }
                }
                *(float2*)(Dptr + (size_t)row * NTOT + col) = make_float2(v0, v1);
            }
        }
    }
}

// ---------------------------------------------------------------------------
// K2: single pass over neigh. Block (128 thr) per b. neigh tile staged in
// smem with XOR-16B swizzle so both access patterns are conflict-free.
// ---------------------------------------------------------------------------
__global__ __launch_bounds__(128) void k2_attn(
    const float* __restrict__ neigh,   // [B][16][256]
    const float* __restrict__ nw)      // [B][16]
{
    const int b = blockIdx.x;
    const int t = threadIdx.x;
    __shared__ float n_sm[KN][260];
    __shared__ float qk_sm[2 * 256];
    __shared__ float s_sm[NH][KN];
    __shared__ float attn_sm[NH][KN];

    {
        const float4 v = __ldg((const float4*)(g_QK + (size_t)b * 512) + t);
        const int h = t >> 6, c4 = t & 63;
        const int phys = c4 ^ ((c4 >> 3) & 7);
        *(float4*)&qk_sm[h * 256 + phys * 4] = v;
    }
    {
        const float4* nsrc = (const float4*)(neigh + (size_t)b * KN * EMB);
        #pragma unroll
        for (int i = 0; i < 8; i++) {
            const int f4 = t + i * 128;
            const int j = f4 >> 6, c4 = f4 & 63;
            const int phys = c4 ^ ((c4 >> 3) & 7);
            const float4 v = __ldg(nsrc + f4);
            *(float4*)&n_sm[j][phys * 4] = v;
        }
    }
    __syncthreads();

    {
        const int j = t >> 3, o = t & 7;
        float a0 = 0.f, a1 = 0.f;
        #pragma unroll
        for (int i = 0; i < 8; i++) {
            const int c4 = o * 8 + i;
            const int phys = c4 ^ o;
            const float4 n  = *(const float4*)&n_sm[j][phys * 4];
            const float4 q0 = *(const float4*)&qk_sm[phys * 4];
            const float4 q1 = *(const float4*)&qk_sm[256 + phys * 4];
            a0 += n.x * q0.x + n.y * q0.y + n.z * q0.z + n.w * q0.w;
            a1 += n.x * q1.x + n.y * q1.y + n.z * q1.z + n.w * q1.w;
        }
        #pragma unroll
        for (int m = 1; m < 8; m <<= 1) {
            a0 += __shfl_xor_sync(0xffffffff, a0, m);
            a1 += __shfl_xor_sync(0xffffffff, a1, m);
        }
        if (o == 0) {
            s_sm[0][j] = a0 * 0.125f;
            s_sm[1][j] = a1 * 0.125f;
        }
    }
    __syncthreads();

    if (t < 2) {
        const int h = t;
        float s[KN];
        float m = -1e30f;
        #pragma unroll
        for (int j = 0; j < KN; j++) { s[j] = s_sm[h][j]; m = fmaxf(m, s[j]); }
        float Se = 0.f;
        #pragma unroll
        for (int j = 0; j < KN; j++) { s[j] = expf(s[j] - m); Se += s[j]; }
        const float inv = 1.0f / Se;
        float den = 0.f;
        #pragma unroll
        for (int j = 0; j < KN; j++) {
            s[j] = s[j] * inv * __ldg(&nw[(size_t)b * KN + j]);
            den += s[j];
        }
        const float invd = 1.0f / (den + 1e-8f);
        #pragma unroll
        for (int j = 0; j < KN; j++) attn_sm[h][j] = s[j] * invd;
    }
    __syncthreads();

    #pragma unroll
    for (int i = 0; i < 4; i++) {
        const int o_idx = t + i * 128;
        const int h = o_idx >> 8, d = o_idx & 255;
        const int c4 = d >> 2;
        const int pd = (c4 ^ ((c4 >> 3) & 7)) * 4 + (d & 3);
        float acc = 0.f;
        #pragma unroll
        for (int j = 0; j < KN; j++)
            acc += attn_sm[h][j] * n_sm[j][pd];
        g_CTX[(size_t)b * 512 + o_idx] = acc;
    }
}

// ---------------------------------------------------------------------------
extern "C" void kernel_launch(void* const* d_in, const int* in_sizes, int n_in,
                              void* d_out, int out_size)
{
    const float* center = (const float*)d_in[0];
    const float* neigh  = (const float*)d_in[1];
    const float* nw     = (const float*)d_in[2];
    const int*   vmask  = (const int*)d_in[3];
    const float* Wq     = (const float*)d_in[4];
    const float* Wk     = (const float*)d_in[5];
    const float* Wout   = (const float*)d_in[6];
    const float* bout   = (const float*)d_in[7];
    float*       out    = (float*)d_out;

    k0_M<<<512, 256>>>(Wq, Wk);
    // QK[32768,512] = center[32768,256] @ M^T
    gemm_tf32<256, true><<<dim3(256, 4), 256>>>(center, nullptr, nullptr, 512,
                                                nullptr, nullptr, nullptr);
    k2_attn<<<B_TOT, 128>>>(neigh, nw);
    // OUT[32768,256] = CTX[32768,512] @ Wout^T + bias, masked
    gemm_tf32<512, false><<<dim3(256, 2), 256>>>(nullptr, Wout, out, 256,
                                                 bout, center, vmask);
}

// round 9
// speedup vs baseline: 9.8595x; 1.0633x over previous
#include <cuda_runtime.h>
#include <cuda_bf16.h>
#include <cstdint>

#define B_TOT 32768
#define EMB   256
#define ADIM  64
#define NH    2
#define KN    16

// Scratch (device globals; no allocation allowed)
__device__ float g_QK [B_TOT * 512];   // [b][h*256+d]
__device__ float g_CTX[B_TOT * 512];   // [b][h*256+d]
__device__ float g_M  [512 * 256];     // [hd][e]

__device__ __forceinline__ void mma_tf32(float c[4], const uint32_t a[4], const uint32_t b[2]) {
    asm volatile(
        "mma.sync.aligned.m16n8k8.row.col.f32.tf32.tf32.f32 "
        "{%0,%1,%2,%3}, {%4,%5,%6,%7}, {%8,%9}, {%0,%1,%2,%3};"
        : "+f"(c[0]), "+f"(c[1]), "+f"(c[2]), "+f"(c[3])
        : "r"(a[0]), "r"(a[1]), "r"(a[2]), "r"(a[3]), "r"(b[0]), "r"(b[1]));
}

__device__ __forceinline__ void cp16(uint32_t dst, const void* src) {
    asm volatile("cp.async.cg.shared.global [%0], [%1], 16;" :: "r"(dst), "l"(src));
}
__device__ __forceinline__ void cp_commit() {
    asm volatile("cp.async.commit_group;");
}
template<int N>
__device__ __forceinline__ void cp_wait() {
    asm volatile("cp.async.wait_group %0;" :: "n"(N));
}

// ---------------------------------------------------------------------------
// K0: g_M[hd][e] = sum_a Wq[h*64+a][e] * Wk[h*64+a][d].  512 blocks x 256 thr.
// ---------------------------------------------------------------------------
__global__ __launch_bounds__(256) void k0_M(
    const float* __restrict__ Wq, const float* __restrict__ Wk)
{
    __shared__ float wk_sm[64];
    const int hd = blockIdx.x, h = hd >> 8, d = hd & 255;
    const int t = threadIdx.x;
    if (t < 64) wk_sm[t] = __ldg(&Wk[(h * 64 + t) * 256 + d]);
    __syncthreads();
    float acc = 0.f;
    #pragma unroll 8
    for (int a = 0; a < 64; a++)
        acc += wk_sm[a] * __ldg(&Wq[(h * 64 + a) * 256 + t]);
    g_M[hd * 256 + t] = acc;
}

// ---------------------------------------------------------------------------
// tf32 GEMM, cp.async 3-stage ring (16-k chunks), ONE barrier per chunk.
// Block tile 128x128, 256 threads (8 warps), warp tile 32(M) x 64(N).
// Smem layout: [stage][row][16] with float4 XOR swizzle c4p = c4 ^ ((row>>1)&3).
// ---------------------------------------------------------------------------
template<int KTOT, bool IS_K1>
__global__ __launch_bounds__(256) void gemm_tf32(
    const float* __restrict__ Ap,
    const float* __restrict__ Bp_in,
    float* __restrict__ Dp_in,
    int NTOT,
    const float* __restrict__ bout,
    const float* __restrict__ center,
    const int* __restrict__ mask)
{
    __shared__ float As[3][128][16];   // 24 KB
    __shared__ float Bs[3][128][16];   // 24 KB  (total 48 KB exactly)

    const float* Aptr = IS_K1 ? Ap   : g_CTX;
    const float* Bptr = IS_K1 ? g_M  : Bp_in;
    float*       Dptr = IS_K1 ? g_QK : Dp_in;

    const int t    = threadIdx.x;
    const int w    = t >> 5, lane = t & 31;
    const int g    = lane >> 2, tid4 = lane & 3;
    const int wm   = w & 3;      // 4 warps along M (32 rows each)
    const int wn   = w >> 2;     // 2 warps along N (64 cols each)
    const int m_blk = blockIdx.x * 128;
    const int n_blk = blockIdx.y * 128;

    const uint32_t a_base = (uint32_t)__cvta_generic_to_shared(&As[0][0][0]);
    const uint32_t b_base = (uint32_t)__cvta_generic_to_shared(&Bs[0][0][0]);

    constexpr int NCH = KTOT / 16;

    // staging coords: idx = t + i*256 -> row = idx>>2 (0..127), kq = idx&3
    const int row_st = t >> 2;        // + i*64
    const int kq_st  = t & 3;

    auto stage = [&](int ch, int buf) {
        #pragma unroll
        for (int i = 0; i < 2; i++) {
            const int row = row_st + i * 64;
            const int c4p = kq_st ^ ((row >> 1) & 3);
            const uint32_t off = (uint32_t)(((buf * 128 + row) * 16 + c4p * 4) * 4);
            cp16(a_base + off, Aptr + (size_t)(m_blk + row) * KTOT + ch * 16 + kq_st * 4);
            cp16(b_base + off, Bptr + (size_t)(n_blk + row) * KTOT + ch * 16 + kq_st * 4);
        }
    };

    float acc[2][8][4];
    #pragma unroll
    for (int mi = 0; mi < 2; mi++)
        #pragma unroll
        for (int ni = 0; ni < 8; ni++)
            #pragma unroll
            for (int i = 0; i < 4; i++) acc[mi][ni][i] = 0.f;

    stage(0, 0); cp_commit();
    stage(1, 1); cp_commit();

    int sl = 0;       // compute slot = ch % 3
    int sn = 2;       // stage slot   = (ch+2) % 3
    for (int ch = 0; ch < NCH; ch++) {
        cp_wait<1>();          // chunk ch resident
        __syncthreads();       // also protects slot sn (last read at iter ch-1)
        if (ch + 2 < NCH) stage(ch + 2, sn);
        cp_commit();           // empty group on tail iters keeps count invariant

        #pragma unroll
        for (int ks = 0; ks < 2; ks++) {
            const int c4a = ks * 2;                  // k0>>2, k0 = ks*8
            uint32_t af[2][4];
            #pragma unroll
            for (int mi = 0; mi < 2; mi++) {
                const int r0 = wm * 32 + mi * 16 + g;
                const int r1 = r0 + 8;
                const int s0 = (r0 >> 1) & 3;
                const int s1 = (r1 >> 1) & 3;
                af[mi][0] = __float_as_uint(As[sl][r0][((c4a    ) ^ s0) * 4 + tid4]);
                af[mi][1] = __float_as_uint(As[sl][r1][((c4a    ) ^ s1) * 4 + tid4]);
                af[mi][2] = __float_as_uint(As[sl][r0][((c4a + 1) ^ s0) * 4 + tid4]);
                af[mi][3] = __float_as_uint(As[sl][r1][((c4a + 1) ^ s1) * 4 + tid4]);
            }
            #pragma unroll
            for (int ni = 0; ni < 8; ni++) {
                const int rb = wn * 64 + ni * 8 + g;
                const int sb = (rb >> 1) & 3;
                uint32_t bf[2];
                bf[0] = __float_as_uint(Bs[sl][rb][((c4a    ) ^ sb) * 4 + tid4]);
                bf[1] = __float_as_uint(Bs[sl][rb][((c4a + 1) ^ sb) * 4 + tid4]);
                mma_tf32(acc[0][ni], af[0], bf);
                mma_tf32(acc[1][ni], af[1], bf);
            }
        }
        sl = (sl == 2) ? 0 : sl + 1;
        sn = (sn == 2) ? 0 : sn + 1;
    }

    // Epilogue.  C frag: c0=(g, 2*tid4), c1=(g, 2*tid4+1), c2=(g+8,..), c3.
    #pragma unroll
    for (int mi = 0; mi < 2; mi++) {
        #pragma unroll
        for (int half = 0; half < 2; half++) {
            const int row = m_blk + wm * 32 + mi * 16 + g + half * 8;
            bool valid = true;
            if (!IS_K1) valid = (__ldg(&mask[row]) != 0);
            #pragma unroll
            for (int ni = 0; ni < 8; ni++) {
                const int col = n_blk + wn * 64 + ni * 8 + tid4 * 2;
                float v0 = acc[mi][ni][half * 2 + 0];
                float v1 = acc[mi][ni][half * 2 + 1];
                if (!IS_K1) {
                    v0 += __ldg(&bout[col]);
                    v1 += __ldg(&bout[col + 1]);
                    if (!valid) {
                        v0 = __ldg(&center[(size_t)row * EMB + col]);
                        v1 = __ldg(&center[(size_t)row * EMB + col + 1]);
                    }
                }
                *(float2*)(Dptr + (size_t)row * NTOT + col) = make_float2(v0, v1);
            }
        }
    }
}

// ---------------------------------------------------------------------------
// K2: single pass over neigh. Block (128 thr) per b. neigh tile staged in
// smem with XOR-16B swizzle via cp.async (no register roundtrip).
// ---------------------------------------------------------------------------
__global__ __launch_bounds__(128) void k2_attn(
    const float* __restrict__ neigh,   // [B][16][256]
    const float* __restrict__ nw)      // [B][16]
{
    const int b = blockIdx.x;
    const int t = threadIdx.x;
    __shared__ float n_sm[KN][260];
    __shared__ float qk_sm[2 * 256];
    __shared__ float s_sm[NH][KN];
    __shared__ float attn_sm[NH][KN];

    const uint32_t qk_base = (uint32_t)__cvta_generic_to_shared(&qk_sm[0]);
    const uint32_t n_base  = (uint32_t)__cvta_generic_to_shared(&n_sm[0][0]);

    // stage QK[b] (128 f4) swizzled
    {
        const int h = t >> 6, c4 = t & 63;
        const int phys = c4 ^ ((c4 >> 3) & 7);
        cp16(qk_base + (uint32_t)((h * 256 + phys * 4) * 4),
             (const float4*)(g_QK + (size_t)b * 512) + t);
    }
    // stage neigh tile (1024 f4) swizzled
    {
        const float4* nsrc = (const float4*)(neigh + (size_t)b * KN * EMB);
        #pragma unroll
        for (int i = 0; i < 8; i++) {
            const int f4 = t + i * 128;
            const int j = f4 >> 6, c4 = f4 & 63;
            const int phys = c4 ^ ((c4 >> 3) & 7);
            cp16(n_base + (uint32_t)((j * 260 + phys * 4) * 4), nsrc + f4);
        }
    }
    cp_commit();
    cp_wait<0>();
    __syncthreads();

    {
        const int j = t >> 3, o = t & 7;
        float a0 = 0.f, a1 = 0.f;
        #pragma unroll
        for (int i = 0; i < 8; i++) {
            const int c4 = o * 8 + i;
            const int phys = c4 ^ o;
            const float4 n  = *(const float4*)&n_sm[j][phys * 4];
            const float4 q0 = *(const float4*)&qk_sm[phys * 4];
            const float4 q1 = *(const float4*)&qk_sm[256 + phys * 4];
            a0 += n.x * q0.x + n.y * q0.y + n.z * q0.z + n.w * q0.w;
            a1 += n.x * q1.x + n.y * q1.y + n.z * q1.z + n.w * q1.w;
        }
        #pragma unroll
        for (int m = 1; m < 8; m <<= 1) {
            a0 += __shfl_xor_sync(0xffffffff, a0, m);
            a1 += __shfl_xor_sync(0xffffffff, a1, m);
        }
        if (o == 0) {
            s_sm[0][j] = a0 * 0.125f;
            s_sm[1][j] = a1 * 0.125f;
        }
    }
    __syncthreads();

    if (t < 2) {
        const int h = t;
        float s[KN];
        float m = -1e30f;
        #pragma unroll
        for (int j = 0; j < KN; j++) { s[j] = s_sm[h][j]; m = fmaxf(m, s[j]); }
        float Se = 0.f;
        #pragma unroll
        for (int j = 0; j < KN; j++) { s[j] = expf(s[j] - m); Se += s[j]; }
        const float inv = 1.0f / Se;
        float den = 0.f;
        #pragma unroll
        for (int j = 0; j < KN; j++) {
            s[j] = s[j] * inv * __ldg(&nw[(size_t)b * KN + j]);
            den += s[j];
        }
        const float invd = 1.0f / (den + 1e-8f);
        #pragma unroll
        for (int j = 0; j < KN; j++) attn_sm[h][j] = s[j] * invd;
    }
    __syncthreads();

    #pragma unroll
    for (int i = 0; i < 4; i++) {
        const int o_idx = t + i * 128;
        const int h = o_idx >> 8, d = o_idx & 255;
        const int c4 = d >> 2;
        const int pd = (c4 ^ ((c4 >> 3) & 7)) * 4 + (d & 3);
        float acc = 0.f;
        #pragma unroll
        for (int j = 0; j < KN; j++)
            acc += attn_sm[h][j] * n_sm[j][pd];
        g_CTX[(size_t)b * 512 + o_idx] = acc;
    }
}

// ---------------------------------------------------------------------------
extern "C" void kernel_launch(void* const* d_in, const int* in_sizes, int n_in,
                              void* d_out, int out_size)
{
    const float* center = (const float*)d_in[0];
    const float* neigh  = (const float*)d_in[1];
    const float* nw     = (const float*)d_in[2];
    const int*   vmask  = (const int*)d_in[3];
    const float* Wq     = (const float*)d_in[4];
    const float* Wk     = (const float*)d_in[5];
    const float* Wout   = (const float*)d_in[6];
    const float* bout   = (const float*)d_in[7];
    float*       out    = (float*)d_out;

    k0_M<<<512, 256>>>(Wq, Wk);
    // QK[32768,512] = center[32768,256] @ M^T
    gemm_tf32<256, true><<<dim3(256, 4), 256>>>(center, nullptr, nullptr, 512,
                                                nullptr, nullptr, nullptr);
    k2_attn<<<B_TOT, 128>>>(neigh, nw);
    // OUT[32768,256] = CTX[32768,512] @ Wout^T + bias, masked
    gemm_tf32<512, false><<<dim3(256, 2), 256>>>(nullptr, Wout, out, 256,
                                                 bout, center, vmask);
}

// round 12
// speedup vs baseline: 10.0335x; 1.0176x over previous
#include <cuda_runtime.h>
#include <cuda_bf16.h>
#include <cstdint>

#define B_TOT 32768
#define EMB   256
#define ADIM  64
#define NH    2
#define KN    16
#define K2_NB 16

// Scratch (device globals; no allocation allowed)
__device__ float g_QK [B_TOT * 512];   // [b][h*256+d]
__device__ float g_CTX[B_TOT * 512];   // [b][h*256+d]
__device__ float g_M  [512 * 256];     // [hd][e]

__device__ __forceinline__ void mma_tf32(float c[4], const uint32_t a[4], const uint32_t b[2]) {
    asm volatile(
        "mma.sync.aligned.m16n8k8.row.col.f32.tf32.tf32.f32 "
        "{%0,%1,%2,%3}, {%4,%5,%6,%7}, {%8,%9}, {%0,%1,%2,%3};"
        : "+f"(c[0]), "+f"(c[1]), "+f"(c[2]), "+f"(c[3])
        : "r"(a[0]), "r"(a[1]), "r"(a[2]), "r"(a[3]), "r"(b[0]), "r"(b[1]));
}

__device__ __forceinline__ void ldsm4(uint32_t& r0, uint32_t& r1, uint32_t& r2, uint32_t& r3,
                                      uint32_t addr) {
    asm volatile("ldmatrix.sync.aligned.m8n8.x4.shared.b16 {%0,%1,%2,%3}, [%4];"
                 : "=r"(r0), "=r"(r1), "=r"(r2), "=r"(r3) : "r"(addr));
}

__device__ __forceinline__ void cp16(uint32_t dst, const void* src) {
    asm volatile("cp.async.cg.shared.global [%0], [%1], 16;" :: "r"(dst), "l"(src));
}
__device__ __forceinline__ void cp_commit() {
    asm volatile("cp.async.commit_group;");
}
template<int N>
__device__ __forceinline__ void cp_wait() {
    asm volatile("cp.async.wait_group %0;" :: "n"(N));
}

// ---------------------------------------------------------------------------
// K0: g_M[hd][e] = sum_a Wq[h*64+a][e] * Wk[h*64+a][d].  512 blocks x 256 thr.
// ---------------------------------------------------------------------------
__global__ __launch_bounds__(256) void k0_M(
    const float* __restrict__ Wq, const float* __restrict__ Wk)
{
    __shared__ float wk_sm[64];
    const int hd = blockIdx.x, h = hd >> 8, d = hd & 255;
    const int t = threadIdx.x;
    if (t < 64) wk_sm[t] = __ldg(&Wk[(h * 64 + t) * 256 + d]);
    __syncthreads();
    float acc = 0.f;
    #pragma unroll 8
    for (int a = 0; a < 64; a++)
        acc += wk_sm[a] * __ldg(&Wq[(h * 64 + a) * 256 + t]);
    g_M[hd * 256 + t] = acc;
}

// ---------------------------------------------------------------------------
// tf32 GEMM, cp.async 3-stage ring (16-k chunks), ldmatrix fragment loads.
// Block tile 128x128, 256 threads (8 warps), warp tile 32(M) x 64(N).
// Smem layout: [stage][row][16] with float4 XOR swizzle c4p = c4 ^ ((row>>1)&3).
// ---------------------------------------------------------------------------
template<int KTOT, bool IS_K1>
__global__ __launch_bounds__(256) void gemm_tf32(
    const float* __restrict__ Ap,
    const float* __restrict__ Bp_in,
    float* __restrict__ Dp_in,
    int NTOT,
    const float* __restrict__ bout,
    const float* __restrict__ center,
    const int* __restrict__ mask)
{
    __shared__ float As[3][128][16];   // 24 KB
    __shared__ float Bs[3][128][16];   // 24 KB

    const float* Aptr = IS_K1 ? Ap   : g_CTX;
    const float* Bptr = IS_K1 ? g_M  : Bp_in;
    float*       Dptr = IS_K1 ? g_QK : Dp_in;

    const int t    = threadIdx.x;
    const int w    = t >> 5, lane = t & 31;
    const int g    = lane >> 2, tid4 = lane & 3;
    const int wm   = w & 3;      // 4 warps along M (32 rows each)
    const int wn   = w >> 2;     // 2 warps along N (64 cols each)
    const int m_blk = blockIdx.x * 128;
    const int n_blk = blockIdx.y * 128;

    const uint32_t a_base = (uint32_t)__cvta_generic_to_shared(&As[0][0][0]);
    const uint32_t b_base = (uint32_t)__cvta_generic_to_shared(&Bs[0][0][0]);

    constexpr int NCH = KTOT / 16;

    // staging coords: idx = t + i*256 -> row = idx>>2 (0..127), kq = idx&3
    const int row_st = t >> 2;        // + i*64
    const int kq_st  = t & 3;

    auto stage = [&](int ch, int buf) {
        #pragma unroll
        for (int i = 0; i < 2; i++) {
            const int row = row_st + i * 64;
            const int c4p = kq_st ^ ((row >> 1) & 3);
            const uint32_t off = (uint32_t)(buf * 8192 + row * 64 + c4p * 16);
            cp16(a_base + off, Aptr + (size_t)(m_blk + row) * KTOT + ch * 16 + kq_st * 4);
            cp16(b_base + off, Bptr + (size_t)(n_blk + row) * KTOT + ch * 16 + kq_st * 4);
        }
    };

    // per-lane ldmatrix geometry
    const int arow0     = wm * 32 + ((lane & 7) | (lane & 8));     // + mi*16
    const int awsel     = (lane >> 4) & 1;
    const int brow0     = wn * 64 + (lane & 7) + ((lane >> 4) & 1) * 8;  // + p*16
    const int bwsel     = (lane >> 3) & 1;

    float acc[2][8][4];
    #pragma unroll
    for (int mi = 0; mi < 2; mi++)
        #pragma unroll
        for (int ni = 0; ni < 8; ni++)
            #pragma unroll
            for (int i = 0; i < 4; i++) acc[mi][ni][i] = 0.f;

    stage(0, 0); cp_commit();
    stage(1, 1); cp_commit();

    int sl = 0;       // compute slot = ch % 3
    int sn = 2;       // stage slot   = (ch+2) % 3
    for (int ch = 0; ch < NCH; ch++) {
        cp_wait<1>();          // chunk ch resident
        __syncthreads();       // also protects slot sn (last read at iter ch-1)
        if (ch + 2 < NCH) stage(ch + 2, sn);
        cp_commit();           // empty group on tail iters keeps count invariant

        #pragma unroll
        for (int ks = 0; ks < 2; ks++) {
            const int c4a = ks * 2;
            uint32_t af[2][4];
            #pragma unroll
            for (int mi = 0; mi < 2; mi++) {
                const int row = arow0 + mi * 16;
                const int sw  = (row >> 1) & 3;
                const uint32_t addr = a_base + (uint32_t)(sl * 8192 + row * 64
                                      + (((c4a + awsel) ^ sw) << 4));
                ldsm4(af[mi][0], af[mi][1], af[mi][2], af[mi][3], addr);
            }
            uint32_t bf[8][2];
            #pragma unroll
            for (int p = 0; p < 4; p++) {
                const int row = brow0 + p * 16;
                const int sw  = (row >> 1) & 3;
                const uint32_t addr = b_base + (uint32_t)(sl * 8192 + row * 64
                                      + (((c4a + bwsel) ^ sw) << 4));
                ldsm4(bf[2 * p][0], bf[2 * p][1], bf[2 * p + 1][0], bf[2 * p + 1][1], addr);
            }
            #pragma unroll
            for (int ni = 0; ni < 8; ni++) {
                mma_tf32(acc[0][ni], af[0], bf[ni]);
                mma_tf32(acc[1][ni], af[1], bf[ni]);
            }
        }
        sl = (sl == 2) ? 0 : sl + 1;
        sn = (sn == 2) ? 0 : sn + 1;
    }

    // Epilogue.  C frag: c0=(g, 2*tid4), c1=(g, 2*tid4+1), c2=(g+8,..), c3.
    #pragma unroll
    for (int mi = 0; mi < 2; mi++) {
        #pragma unroll
        for (int half = 0; half < 2; half++) {
            const int row = m_blk + wm * 32 + mi * 16 + g + half * 8;
            bool valid = true;
            if (!IS_K1) valid = (__ldg(&mask[row]) != 0);
            #pragma unroll
            for (int ni = 0; ni < 8; ni++) {
                const int col = n_blk + wn * 64 + ni * 8 + tid4 * 2;
                float v0 = acc[mi][ni][half * 2 + 0];
                float v1 = acc[mi][ni][half * 2 + 1];
                if (!IS_K1) {
                    v0 += __ldg(&bout[col]);
                    v1 += __ldg(&bout[col + 1]);
                    if (!valid) {
                        v0 = __ldg(&center[(size_t)row * EMB + col]);
                        v1 = __ldg(&center[(size_t)row * EMB + col + 1]);
                    }
                }
                *(float2*)(Dptr + (size_t)row * NTOT + col) = make_float2(v0, v1);
            }
        }
    }
}

// ---------------------------------------------------------------------------
// K2: block handles K2_NB consecutive rows with double-buffered cp.async so
// the DRAM stream overlaps compute.  128 threads, XOR-16B swizzled smem.
// ---------------------------------------------------------------------------
__global__ __launch_bounds__(128) void k2_attn(
    const float* __restrict__ neigh,   // [B][16][256]
    const float* __restrict__ nw)      // [B][16]
{
    const int b0 = blockIdx.x * K2_NB;
    const int t  = threadIdx.x;
    __shared__ float n_sm[2][KN][260];     // 33.3 KB
    __shared__ float qk_sm[2][512];        // 4 KB
    __shared__ float s_sm[NH][KN];
    __shared__ float attn_sm[NH][KN];
    __shared__ float nw_sm[K2_NB][KN];

    const uint32_t qk_base = (uint32_t)__cvta_generic_to_shared(&qk_sm[0][0]);
    const uint32_t n_base  = (uint32_t)__cvta_generic_to_shared(&n_sm[0][0][0]);

    // preload weights for all K2_NB rows (256 floats = 64 f4)
    if (t < 64)
        ((float4*)&nw_sm[0][0])[t] = __ldg((const float4*)(nw + (size_t)b0 * KN) + t);

    auto stage = [&](int i, int buf) {
        {
            const int h = t >> 6, c4 = t & 63;
            const int phys = c4 ^ ((c4 >> 3) & 7);
            cp16(qk_base + (uint32_t)((buf * 512 + h * 256 + phys * 4) * 4),
                 (const float4*)(g_QK + (size_t)(b0 + i) * 512) + t);
        }
        const float4* nsrc = (const float4*)(neigh + (size_t)(b0 + i) * KN * EMB);
        #pragma unroll
        for (int u = 0; u < 8; u++) {
            const int f4 = t + u * 128;
            const int j = f4 >> 6, c4 = f4 & 63;
            const int phys = c4 ^ ((c4 >> 3) & 7);
            cp16(n_base + (uint32_t)((((buf * KN) + j) * 260 + phys * 4) * 4), nsrc + f4);
        }
    };

    stage(0, 0);
    cp_commit();

    for (int i = 0; i < K2_NB; i++) {
        const int buf = i & 1;
        if (i + 1 < K2_NB) stage(i + 1, buf ^ 1);
        cp_commit();           // empty group on the tail keeps count invariant
        cp_wait<1>();
        __syncthreads();

        // dot phase: thread (j = t>>3, o = t&7), both heads per n read
        {
            const int j = t >> 3, o = t & 7;
            float a0 = 0.f, a1 = 0.f;
            #pragma unroll
            for (int u = 0; u < 8; u++) {
                const int c4 = o * 8 + u;
                const int phys = c4 ^ o;
                const float4 n  = *(const float4*)&n_sm[buf][j][phys * 4];
                const float4 q0 = *(const float4*)&qk_sm[buf][phys * 4];
                const float4 q1 = *(const float4*)&qk_sm[buf][256 + phys * 4];
                a0 += n.x * q0.x + n.y * q0.y + n.z * q0.z + n.w * q0.w;
                a1 += n.x * q1.x + n.y * q1.y + n.z * q1.z + n.w * q1.w;
            }
            #pragma unroll
            for (int m = 1; m < 8; m <<= 1) {
                a0 += __shfl_xor_sync(0xffffffff, a0, m);
                a1 += __shfl_xor_sync(0xffffffff, a1, m);
            }
            if (o == 0) {
                s_sm[0][j] = a0 * 0.125f;
                s_sm[1][j] = a1 * 0.125f;
            }
        }
        __syncthreads();

        if (t < 2) {
            const int h = t;
            float s[KN];
            float m = -1e30f;
            #pragma unroll
            for (int j = 0; j < KN; j++) { s[j] = s_sm[h][j]; m = fmaxf(m, s[j]); }
            float Se = 0.f;
            #pragma unroll
            for (int j = 0; j < KN; j++) { s[j] = expf(s[j] - m); Se += s[j]; }
            const float inv = 1.0f / Se;
            float den = 0.f;
            #pragma unroll
            for (int j = 0; j < KN; j++) {
                s[j] = s[j] * inv * nw_sm[i][j];
                den += s[j];
            }
            const float invd = 1.0f / (den + 1e-8f);
            #pragma unroll
            for (int j = 0; j < KN; j++) attn_sm[h][j] = s[j] * invd;
        }
        __syncthreads();

        #pragma unroll
        for (int u = 0; u < 4; u++) {
            const int o_idx = t + u * 128;
            const int h = o_idx >> 8, d = o_idx & 255;
            const int c4 = d >> 2;
            const int pd = (c4 ^ ((c4 >> 3) & 7)) * 4 + (d & 3);
            float acc = 0.f;
            #pragma unroll
            for (int j = 0; j < KN; j++)
                acc += attn_sm[h][j] * n_sm[buf][j][pd];
            g_CTX[(size_t)(b0 + i) * 512 + o_idx] = acc;
        }
        __syncthreads();   // protect s_sm/attn_sm and buf^1 overwrite next iter
    }
}

// ---------------------------------------------------------------------------
extern "C" void kernel_launch(void* const* d_in, const int* in_sizes, int n_in,
                              void* d_out, int out_size)
{
    const float* center = (const float*)d_in[0];
    const float* neigh  = (const float*)d_in[1];
    const float* nw     = (const float*)d_in[2];
    const int*   vmask  = (const int*)d_in[3];
    const float* Wq     = (const float*)d_in[4];
    const float* Wk     = (const float*)d_in[5];
    const float* Wout   = (const float*)d_in[6];
    const float* bout   = (const float*)d_in[7];
    float*       out    = (float*)d_out;

    k0_M<<<512, 256>>>(Wq, Wk);
    // QK[32768,512] = center[32768,256] @ M^T
    gemm_tf32<256, true><<<dim3(256, 4), 256>>>(center, nullptr, nullptr, 512,
                                                nullptr, nullptr, nullptr);
    k2_attn<<<B_TOT / K2_NB, 128>>>(neigh, nw);
    // OUT[32768,256] = CTX[32768,512] @ Wout^T + bias, masked
    gemm_tf32<512, false><<<dim3(256, 2), 256>>>(nullptr, Wout, out, 256,
                                                 bout, center, vmask);
}